// round 1
// baseline (speedup 1.0000x reference)
#include <cuda_runtime.h>
#include <cuda_bf16.h>
#include <math.h>

// Problem constants (fixed by reference setup_inputs)
#define SEQ   16
#define NT    32
#define NA    64
#define BJ    2048          // nt*na  (time-major batch)
#define H     512
#define K2    1024          // 2*H (x | h concat)
#define G4    2048          // 4*H gates
#define BSB   512           // bs = nt*seq_len
#define OUT_HALF (BSB*NA*H) // 16,777,216 floats per output tensor

// ---------------- persistent device scratch (no allocations allowed) -------
__device__ float g_A[SEQ * BJ * K2];   // per-step GEMM A: [t][j][ x(512) | h(512) ]  128 MB
__device__ float g_W[G4 * K2];         // Wcat[m][k] = [W_ih | W_hh]                     8 MB
__device__ float g_bias[G4];           // b_ih + b_hh
__device__ float g_gates[BJ * G4];     // per-step gates scratch                        16 MB
__device__ float g_c[BJ * H];          // carried cell state (with next reset applied)   4 MB

// ---------------- prep kernels --------------------------------------------
__global__ void prep_weights(const float* __restrict__ W_ih,
                             const float* __restrict__ W_hh,
                             const float* __restrict__ b_ih,
                             const float* __restrict__ b_hh) {
    int idx = blockIdx.x * blockDim.x + threadIdx.x;   // over G4*K2 = 2,097,152
    if (idx >= G4 * K2) return;
    int m = idx >> 10;          // /1024
    int k = idx & 1023;
    float v = (k < H) ? W_ih[m * H + k] : W_hh[m * H + (k - H)];
    g_W[idx] = v;
    if (idx < G4) g_bias[idx] = b_ih[idx] + b_hh[idx];
}

// fill x-halves of g_A for all timesteps
__global__ void prep_x(const float* __restrict__ h_self,
                       const float* __restrict__ h_inter) {
    long long idx = (long long)blockIdx.x * blockDim.x + threadIdx.x; // SEQ*BJ*H = 16,777,216
    if (idx >= (long long)SEQ * BJ * H) return;
    int t   = (int)(idx >> 20);            // / (BJ*H) = /2^20
    int rem = (int)(idx & ((1 << 20) - 1));
    int j = rem >> 9;                      // /512
    int k = rem & 511;
    int n = j >> 6, a = j & 63;
    int b = n * SEQ + t;
    float v;
    if (k < 256) v = h_self[((long long)b * NA + a) * 512 + 256 + k];   // h_self inner dim = 2*N_ATTN = 512
    else         v = h_inter[((long long)b * NA + a) * 256 + (k - 256)];
    g_A[((long long)t * BJ + j) * K2 + k] = v;
}

// initial h/c with reset for t=0 applied
__global__ void prep_state(const float* __restrict__ hxs,
                           const float* __restrict__ cxs,
                           const float* __restrict__ reset) {
    int idx = blockIdx.x * blockDim.x + threadIdx.x;   // BJ*H = 1,048,576
    if (idx >= BJ * H) return;
    int j = idx >> 9;
    int k = idx & 511;
    int n = j >> 6, a = j & 63;
    int b0 = n * SEQ;                       // first timestep of trajectory n
    float s = 1.0f - reset[b0];
    long long src = ((long long)b0 * NA + a) * H + k;
    g_A[(long long)j * K2 + H + k] = hxs[src] * s;   // h-half of g_A[t=0]
    g_c[idx] = cxs[src] * s;
}

// ---------------- per-step SGEMM: gates = bias + A_t @ Wcat^T -------------
// M = BJ = 2048 (j), N = G4 = 2048 (m), K = K2 = 1024. Both operands K-major.
#define BM 128
#define BN 128
#define BKT 16
#define TM 8
#define TN 8

__global__ __launch_bounds__(256, 2)
void gemm_step(const float* __restrict__ A,   // g_A + t*BJ*K2
               float* __restrict__ gates) {
    __shared__ float As[BKT][BM + 4];
    __shared__ float Bs[BKT][BN + 4];

    const int bm = blockIdx.y * BM;   // j tile
    const int bn = blockIdx.x * BN;   // m tile
    const int tid = threadIdx.x;
    const int ty = tid >> 4;          // 0..15
    const int tx = tid & 15;          // 0..15
    const int tm0 = ty * TM;
    const int tn0 = tx * TN;

    float acc[TM][TN];
#pragma unroll
    for (int r = 0; r < TM; r++)
#pragma unroll
        for (int c = 0; c < TN; c++) acc[r][c] = 0.0f;

    const float* Ab = A + (long long)bm * K2;
    const float* Bb = g_W + (long long)bn * K2;

    for (int k0 = 0; k0 < K2; k0 += BKT) {
        // load BM x BKT of A and BN x BKT of W, transposed into shared
#pragma unroll
        for (int l = 0; l < 2; l++) {
            int q   = tid + l * 256;        // 0..511
            int row = q >> 2;               // 0..127
            int kq  = (q & 3) * 4;          // 0,4,8,12
            float4 va = *(const float4*)(Ab + (long long)row * K2 + k0 + kq);
            As[kq + 0][row] = va.x; As[kq + 1][row] = va.y;
            As[kq + 2][row] = va.z; As[kq + 3][row] = va.w;
            float4 vb = *(const float4*)(Bb + (long long)row * K2 + k0 + kq);
            Bs[kq + 0][row] = vb.x; Bs[kq + 1][row] = vb.y;
            Bs[kq + 2][row] = vb.z; Bs[kq + 3][row] = vb.w;
        }
        __syncthreads();

#pragma unroll
        for (int kk = 0; kk < BKT; kk++) {
            float4 a0 = *(const float4*)&As[kk][tm0];
            float4 a1 = *(const float4*)&As[kk][tm0 + 4];
            float4 b0 = *(const float4*)&Bs[kk][tn0];
            float4 b1 = *(const float4*)&Bs[kk][tn0 + 4];
            float ar[TM] = {a0.x, a0.y, a0.z, a0.w, a1.x, a1.y, a1.z, a1.w};
            float br[TN] = {b0.x, b0.y, b0.z, b0.w, b1.x, b1.y, b1.z, b1.w};
#pragma unroll
            for (int r = 0; r < TM; r++)
#pragma unroll
                for (int c = 0; c < TN; c++)
                    acc[r][c] = fmaf(ar[r], br[c], acc[r][c]);
        }
        __syncthreads();
    }

    // epilogue: add bias, store
    float4 bia0 = *(const float4*)&g_bias[bn + tn0];
    float4 bia1 = *(const float4*)&g_bias[bn + tn0 + 4];
    float bb[TN] = {bia0.x, bia0.y, bia0.z, bia0.w, bia1.x, bia1.y, bia1.z, bia1.w};
#pragma unroll
    for (int r = 0; r < TM; r++) {
        float* dst = gates + (long long)(bm + tm0 + r) * G4 + bn + tn0;
        float4 o0 = make_float4(acc[r][0] + bb[0], acc[r][1] + bb[1],
                                acc[r][2] + bb[2], acc[r][3] + bb[3]);
        float4 o1 = make_float4(acc[r][4] + bb[4], acc[r][5] + bb[5],
                                acc[r][6] + bb[6], acc[r][7] + bb[7]);
        *(float4*)(dst)     = o0;
        *(float4*)(dst + 4) = o1;
    }
}

// ---------------- fused LSTM cell + output + next-step staging ------------
__device__ __forceinline__ float sigm(float x) {
    return 1.0f / (1.0f + __expf(-x));
}

__global__ void cell_step(const float* __restrict__ reset,
                          float* __restrict__ out, int t) {
    int idx = blockIdx.x * blockDim.x + threadIdx.x;   // BJ*H
    if (idx >= BJ * H) return;
    int j = idx >> 9;
    int u = idx & 511;
    int n = j >> 6, a = j & 63;

    const float* gr = g_gates + (long long)j * G4;
    float zi = gr[u];
    float zf = gr[u + 512];
    float zg = gr[u + 1024];
    float zo = gr[u + 1536];

    float ii = sigm(zi);
    float ff = sigm(zf);
    float gg = tanhf(zg);
    float oo = sigm(zo);

    float c = ff * g_c[idx] + ii * gg;
    float h = oo * tanhf(c);

    // write outputs at [b = n*SEQ + t][a][u]
    long long o = ((long long)(n * SEQ + t) * NA + a) * H + u;
    out[o]            = h;
    out[o + OUT_HALF] = c;

    // stage next step's inputs with reset pre-applied
    if (t < SEQ - 1) {
        float s = 1.0f - reset[n * SEQ + t + 1];
        g_A[((long long)(t + 1) * BJ + j) * K2 + H + u] = h * s;
        g_c[idx] = c * s;
    }
}

// ---------------- launch ---------------------------------------------------
extern "C" void kernel_launch(void* const* d_in, const int* in_sizes, int n_in,
                              void* d_out, int out_size) {
    const float* h_self  = (const float*)d_in[0];
    const float* h_inter = (const float*)d_in[1];
    const float* hxs     = (const float*)d_in[2];
    const float* cxs     = (const float*)d_in[3];
    const float* reset   = (const float*)d_in[4];
    const float* W_ih    = (const float*)d_in[5];
    const float* W_hh    = (const float*)d_in[6];
    const float* b_ih    = (const float*)d_in[7];
    const float* b_hh    = (const float*)d_in[8];
    float* out = (float*)d_out;

    prep_weights<<<(G4 * K2 + 255) / 256, 256>>>(W_ih, W_hh, b_ih, b_hh);
    prep_x<<<(SEQ * BJ * H + 255) / 256, 256>>>(h_self, h_inter);
    prep_state<<<(BJ * H + 255) / 256, 256>>>(hxs, cxs, reset);

    float* gatesP;
    float* aBase;
    cudaGetSymbolAddress((void**)&gatesP, g_gates);
    cudaGetSymbolAddress((void**)&aBase, g_A);

    dim3 ggrid(G4 / BN, BJ / BM);   // 16 x 16
    for (int t = 0; t < SEQ; t++) {
        gemm_step<<<ggrid, 256>>>(aBase + (long long)t * BJ * K2, gatesP);
        cell_step<<<(BJ * H + 255) / 256, 256>>>(reset, out, t);
    }
}

// round 4
// speedup vs baseline: 1.8321x; 1.8321x over previous
#include <cuda_runtime.h>
#include <cuda_bf16.h>
#include <math.h>
#include <stdint.h>

// ---------------- problem constants ---------------------------------------
#define SEQ   16
#define NA    64
#define BJ    2048          // nt*na
#define H     512
#define K2    1024          // 2*H
#define G4    2048          // 4*H (permuted: col m' = unit*4 + gate)
#define OUT_HALF (512*NA*H)

// ---------------- tile config ---------------------------------------------
#define MT    128
#define NT_   128
#define KC    32            // bf16 k per chunk
#define NCHUNK (K2/KC)      // 32
#define THREADS 256

// smem: 2 stages of (Ah|Al|Bh|Bl) 8KB each = 32KB/stage.
// The gates staging tile ALIASES the stage buffers (stages are dead by then:
// the K-loop's final __syncthreads() orders all ldmatrix reads before reuse).
#define STAGE_SZ   32768
#define GSTRIDE    132                 // floats per gates row (pad)
#define GATES_BYTES (MT*GSTRIDE*4)     // 67584
#define SMEM_BYTES  (GATES_BYTES > 2*STAGE_SZ ? GATES_BYTES : 2*STAGE_SZ)

// ---------------- persistent device scratch --------------------------------
__device__ __nv_bfloat16 g_Ah[SEQ * BJ * K2];   // 64MB  [t][j][x|h]
__device__ __nv_bfloat16 g_Al[SEQ * BJ * K2];   // 64MB
__device__ __nv_bfloat16 g_Wh[G4 * K2];         // 4MB   (rows permuted)
__device__ __nv_bfloat16 g_Wl[G4 * K2];         // 4MB
__device__ float g_biasP[G4];
__device__ float g_c[BJ * H];                   // 4MB (reset pre-applied)

// ---------------- helpers ---------------------------------------------------
__device__ __forceinline__ uint32_t smem_u32(const void* p) {
    uint32_t a;
    asm("{ .reg .u64 t; cvta.to.shared.u64 t, %1; cvt.u32.u64 %0, t; }" : "=r"(a) : "l"(p));
    return a;
}
__device__ __forceinline__ void cp_async16(uint32_t saddr, const void* gaddr) {
    asm volatile("cp.async.cg.shared.global [%0], [%1], 16;" :: "r"(saddr), "l"(gaddr));
}
__device__ __forceinline__ void cp_commit() {
    asm volatile("cp.async.commit_group;" ::: "memory");
}
__device__ __forceinline__ void ldsm4(uint32_t& r0, uint32_t& r1, uint32_t& r2,
                                      uint32_t& r3, uint32_t addr) {
    asm volatile("ldmatrix.sync.aligned.m8n8.x4.shared.b16 {%0,%1,%2,%3}, [%4];"
                 : "=r"(r0), "=r"(r1), "=r"(r2), "=r"(r3) : "r"(addr));
}
__device__ __forceinline__ void mma16816(float* d, const uint32_t* a,
                                         uint32_t b0, uint32_t b1) {
    asm volatile(
        "mma.sync.aligned.m16n8k16.row.col.f32.bf16.bf16.f32 "
        "{%0,%1,%2,%3}, {%4,%5,%6,%7}, {%8,%9}, {%0,%1,%2,%3};"
        : "+f"(d[0]), "+f"(d[1]), "+f"(d[2]), "+f"(d[3])
        : "r"(a[0]), "r"(a[1]), "r"(a[2]), "r"(a[3]), "r"(b0), "r"(b1));
}
__device__ __forceinline__ float sigm(float x) { return 1.0f / (1.0f + __expf(-x)); }
__device__ __forceinline__ void split2(float v, __nv_bfloat16& hi, __nv_bfloat16& lo) {
    hi = __float2bfloat16(v);
    lo = __float2bfloat16(v - __bfloat162float(hi));
}

// ---------------- prep kernels ---------------------------------------------
__global__ void prep_weights(const float* __restrict__ W_ih,
                             const float* __restrict__ W_hh,
                             const float* __restrict__ b_ih,
                             const float* __restrict__ b_hh) {
    int idx = blockIdx.x * blockDim.x + threadIdx.x;   // G4*K2
    if (idx >= G4 * K2) return;
    int mp = idx >> 10;
    int k  = idx & 1023;
    int u = mp >> 2, g = mp & 3;
    int m = g * H + u;
    float v = (k < H) ? W_ih[m * H + k] : W_hh[m * H + (k - H)];
    __nv_bfloat16 hi, lo; split2(v, hi, lo);
    g_Wh[idx] = hi; g_Wl[idx] = lo;
    if (idx < G4) {
        int uu = idx >> 2, gg = idx & 3;
        g_biasP[idx] = b_ih[gg * H + uu] + b_hh[gg * H + uu];
    }
}

__global__ void prep_x(const float* __restrict__ h_self,
                       const float* __restrict__ h_inter) {
    long long idx = (long long)blockIdx.x * blockDim.x + threadIdx.x; // SEQ*BJ*512
    if (idx >= (long long)SEQ * BJ * H) return;
    int t   = (int)(idx >> 20);
    int rem = (int)(idx & ((1 << 20) - 1));
    int j = rem >> 9;
    int k = rem & 511;
    int n = j >> 6, a = j & 63;
    int b = n * SEQ + t;
    float v;
    if (k < 256) v = h_self[((long long)b * NA + a) * 512 + 256 + k];
    else         v = h_inter[((long long)b * NA + a) * 256 + (k - 256)];
    __nv_bfloat16 hi, lo; split2(v, hi, lo);
    long long o = ((long long)t * BJ + j) * K2 + k;
    g_Ah[o] = hi; g_Al[o] = lo;
}

__global__ void prep_state(const float* __restrict__ hxs,
                           const float* __restrict__ cxs,
                           const float* __restrict__ reset) {
    int idx = blockIdx.x * blockDim.x + threadIdx.x;   // BJ*H
    if (idx >= BJ * H) return;
    int j = idx >> 9;
    int k = idx & 511;
    int n = j >> 6, a = j & 63;
    int b0 = n * SEQ;
    float s = 1.0f - reset[b0];
    long long src = ((long long)b0 * NA + a) * H + k;
    float hv = hxs[src] * s;
    __nv_bfloat16 hi, lo; split2(hv, hi, lo);
    long long o = (long long)j * K2 + H + k;
    g_Ah[o] = hi; g_Al[o] = lo;
    g_c[idx] = cxs[src] * s;
}

// ---------------- fused step kernel ----------------------------------------
__global__ __launch_bounds__(THREADS, 1)
void step_kernel(int t, float* __restrict__ out, const float* __restrict__ reset) {
    extern __shared__ char smem[];
    const uint32_t sbase = smem_u32(smem);
    const int tid  = threadIdx.x;
    const int wid  = tid >> 5;
    const int lane = tid & 31;
    const int wm = wid & 3;          // M slice (32 rows)
    const int wn = wid >> 2;         // N slice (64 cols)
    const int mb = blockIdx.y * MT;
    const int nb = blockIdx.x * NT_;

    // ---- per-thread load plan (8 x 16B sectors per chunk) ----
    const char* Ah_b = (const char*)g_Ah + ((size_t)t * BJ + mb) * (K2 * 2);
    const char* Al_b = (const char*)g_Al + ((size_t)t * BJ + mb) * (K2 * 2);
    const char* Wh_b = (const char*)g_Wh + (size_t)nb * (K2 * 2);
    const char* Wl_b = (const char*)g_Wl + (size_t)nb * (K2 * 2);
    const char* gb[8];
    uint32_t so[8];
#pragma unroll
    for (int i = 0; i < 8; i++) {
        int q = tid + i * 256;
        int sub = q >> 9;
        int r = (q & 511) >> 2;
        int cc = q & 3;
        const char* base = (sub == 0) ? Ah_b : (sub == 1) ? Al_b
                          : (sub == 2) ? Wh_b : Wl_b;
        gb[i] = base + (size_t)r * (K2 * 2) + cc * 16;
        so[i] = sub * 8192 + r * 64 + ((cc ^ ((r >> 1) & 3)) * 16);
    }

    // ---- accumulators ----
    float acc[2][8][4];
#pragma unroll
    for (int mt = 0; mt < 2; mt++)
#pragma unroll
        for (int nt = 0; nt < 8; nt++)
#pragma unroll
            for (int q = 0; q < 4; q++) acc[mt][nt][q] = 0.0f;

    // ---- prologue load chunk 0 ----
    {
        const uint32_t st = sbase;
#pragma unroll
        for (int i = 0; i < 8; i++) cp_async16(st + so[i], gb[i]);
        cp_commit();
    }

    // ---- main K loop ----
    const int a_row = (lane & 15);
    const int hi    = (lane >> 4);

    for (int c = 0; c < NCHUNK; c++) {
        if (c + 1 < NCHUNK) {
            const uint32_t st = sbase + ((c + 1) & 1) * STAGE_SZ;
            const int kb = (c + 1) * 64;
#pragma unroll
            for (int i = 0; i < 8; i++) cp_async16(st + so[i], gb[i] + kb);
            cp_commit();
            asm volatile("cp.async.wait_group 1;" ::: "memory");
        } else {
            asm volatile("cp.async.wait_group 0;" ::: "memory");
        }
        __syncthreads();

        const uint32_t st = sbase + (c & 1) * STAGE_SZ;
#pragma unroll
        for (int kk = 0; kk < 2; kk++) {
            uint32_t ah[2][4], al[2][4];
#pragma unroll
            for (int mt = 0; mt < 2; mt++) {
                int row = wm * 32 + mt * 16 + a_row;
                int ch = (kk * 2 + hi) ^ ((row >> 1) & 3);
                uint32_t ad = st + row * 64 + ch * 16;
                ldsm4(ah[mt][0], ah[mt][1], ah[mt][2], ah[mt][3], ad);
                ldsm4(al[mt][0], al[mt][1], al[mt][2], al[mt][3], ad + 8192);
            }
            uint32_t bh[4][4], bl[4][4];
#pragma unroll
            for (int np = 0; np < 4; np++) {
                int row = wn * 64 + np * 16 + a_row;
                int ch = (kk * 2 + hi) ^ ((row >> 1) & 3);
                uint32_t bd = st + 16384 + row * 64 + ch * 16;
                ldsm4(bh[np][0], bh[np][1], bh[np][2], bh[np][3], bd);
                ldsm4(bl[np][0], bl[np][1], bl[np][2], bl[np][3], bd + 8192);
            }
#pragma unroll
            for (int mt = 0; mt < 2; mt++)
#pragma unroll
                for (int nt = 0; nt < 8; nt++) {
                    int np = nt >> 1, od = nt & 1;
                    mma16816(acc[mt][nt], ah[mt], bh[np][od], bh[np][2 + od]);
                    mma16816(acc[mt][nt], ah[mt], bl[np][od], bl[np][2 + od]);
                    mma16816(acc[mt][nt], al[mt], bh[np][od], bh[np][2 + od]);
                }
        }
        __syncthreads();
    }

    // ---- stage accumulators to smem gates tile (aliases dead stage bufs) ----
    float* gsm = (float*)smem;
#pragma unroll
    for (int mt = 0; mt < 2; mt++)
#pragma unroll
        for (int nt = 0; nt < 8; nt++) {
            int r0 = wm * 32 + mt * 16 + (lane >> 2);
            int col = wn * 64 + nt * 8 + (lane & 3) * 2;
            *(float2*)&gsm[r0 * GSTRIDE + col]       = make_float2(acc[mt][nt][0], acc[mt][nt][1]);
            *(float2*)&gsm[(r0 + 8) * GSTRIDE + col] = make_float2(acc[mt][nt][2], acc[mt][nt][3]);
        }
    __syncthreads();

    // ---- fused LSTM cell epilogue ----
    {
        const int jr = tid >> 1;            // 0..127
        const int uh = tid & 1;             // half of the 32 units
        const int j  = mb + jr;
        const int n  = j >> 6, a = j & 63;
        const float sc_next = (t < SEQ - 1) ? (1.0f - reset[n * SEQ + t + 1]) : 0.0f;
        const long long ob = ((long long)(n * SEQ + t) * NA + a) * H;

#pragma unroll 4
        for (int q = 0; q < 16; q++) {
            int ul = uh * 16 + q;                 // 0..31 within tile
            int ug = (nb >> 2) + ul;              // global unit 0..511
            float4 z  = *(float4*)&gsm[jr * GSTRIDE + ul * 4];
            float4 bi = *(const float4*)&g_biasP[nb + ul * 4];
            float ii = sigm(z.x + bi.x);
            float ff = sigm(z.y + bi.y);
            float gg = tanhf(z.z + bi.z);
            float oo = sigm(z.w + bi.w);
            float cold = g_c[j * H + ug];
            float cv = ff * cold + ii * gg;
            float hv = oo * tanhf(cv);
            out[ob + ug]            = hv;
            out[ob + ug + OUT_HALF] = cv;
            if (t < SEQ - 1) {
                __nv_bfloat16 hh, hl;
                split2(hv * sc_next, hh, hl);
                long long ao = ((long long)(t + 1) * BJ + j) * K2 + H + ug;
                g_Ah[ao] = hh;
                g_Al[ao] = hl;
                g_c[j * H + ug] = cv * sc_next;
            }
        }
    }
}

// ---------------- launch ---------------------------------------------------
extern "C" void kernel_launch(void* const* d_in, const int* in_sizes, int n_in,
                              void* d_out, int out_size) {
    const float* h_self  = (const float*)d_in[0];
    const float* h_inter = (const float*)d_in[1];
    const float* hxs     = (const float*)d_in[2];
    const float* cxs     = (const float*)d_in[3];
    const float* reset   = (const float*)d_in[4];
    const float* W_ih    = (const float*)d_in[5];
    const float* W_hh    = (const float*)d_in[6];
    const float* b_ih    = (const float*)d_in[7];
    const float* b_hh    = (const float*)d_in[8];
    float* out = (float*)d_out;

    cudaFuncSetAttribute(step_kernel, cudaFuncAttributeMaxDynamicSharedMemorySize,
                         SMEM_BYTES);

    prep_weights<<<(G4 * K2 + 255) / 256, 256>>>(W_ih, W_hh, b_ih, b_hh);
    prep_x<<<(SEQ * BJ * H + 255) / 256, 256>>>(h_self, h_inter);
    prep_state<<<(BJ * H + 255) / 256, 256>>>(hxs, cxs, reset);

    dim3 grid(G4 / NT_, BJ / MT);   // 16 x 16 = 256 CTAs
    for (int t = 0; t < SEQ; t++) {
        step_kernel<<<grid, THREADS, SMEM_BYTES>>>(t, out, reset);
    }
}